// round 4
// baseline (speedup 1.0000x reference)
#include <cuda_runtime.h>
#include <math.h>
#include <stdint.h>

#define NN 80
#define PAIRS (NN * NN)              // 6400
#define MAX_ITERS 60
#define TOL 1e-3f
#define TPB 512                      // 16 warps
#define ARR_FLOATS (NN * NN)         // 6400 floats = 25600 B per array
#define STAGE_FLOATS (3 * ARR_FLOATS)
#define STAGE_BYTES (STAGE_FLOATS * 4)   // 76800 B per stage

__global__ void zero_out(float* __restrict__ out) {
    out[threadIdx.x] = 0.0f;         // d_out poisoned; we accumulate atomically
}

__device__ __forceinline__ void cp16(uint32_t dst_smem, const float* src) {
    asm volatile("cp.async.cg.shared.global [%0], [%1], 16;"
                 :: "r"(dst_smem), "l"(src));
}
__device__ __forceinline__ void cp_commit() {
    asm volatile("cp.async.commit_group;");
}
template <int N>
__device__ __forceinline__ void cp_wait() {
    asm volatile("cp.async.wait_group %0;" :: "n"(N));
}

// Issue async copy of pair p's three 25.6KB arrays into smem stage buffer.
__device__ __forceinline__ void issue_stage(float* sbuf, int stage, int p,
                                            const float* __restrict__ wr,
                                            const float* __restrict__ rz,
                                            const float* __restrict__ rc,
                                            int tid) {
    const size_t base = (size_t)p * ARR_FLOATS;
    uint32_t d = (uint32_t)__cvta_generic_to_shared(sbuf + stage * STAGE_FLOATS);
    const float* s0 = wr + base;
    const float* s1 = rz + base;
    const float* s2 = rc + base;
    // 1600 16B chunks per array, striped over 512 threads (coalesced).
    for (int i = tid; i < ARR_FLOATS / 4; i += TPB) {
        const uint32_t db = d + i * 16;
        cp16(db,                      s0 + i * 4);
        cp16(db + ARR_FLOATS * 4,     s1 + i * 4);
        cp16(db + 2 * ARR_FLOATS * 4, s2 + i * 4);
    }
}

__global__ __launch_bounds__(TPB, 1)
void power_pipe(const float* __restrict__ r_zeros,
                const float* __restrict__ r_const,
                const float* __restrict__ t_paths,
                const float* __restrict__ weights_t,
                const float* __restrict__ weights_r,
                float* __restrict__ out, int grid) {
    extern __shared__ float sbuf[];      // 2 * 19200 floats = 153.6 KB
    __shared__ float v[NN];
    __shared__ float wv[NN];
    __shared__ float red_ww[16];
    __shared__ float red_vw[16];
    __shared__ float s_n2;
    __shared__ float s_ev;

    const int tid  = threadIdx.x;
    const int warp = tid >> 5;           // 0..15
    const int lane = tid & 31;

    int p = blockIdx.x;
    issue_stage(sbuf, 0, p, weights_r, r_zeros, r_const, tid);
    cp_commit();
    int stage = 0;

    for (; p < PAIRS; p += grid) {
        const int pn = p + grid;
        if (pn < PAIRS) {
            // Prefetch next pair into the other buffer (safe: that buffer was
            // last read two iterations ago, past a __syncthreads).
            issue_stage(sbuf, stage ^ 1, pn, weights_r, r_zeros, r_const, tid);
            cp_commit();
            cp_wait<1>();                // current stage's group done
        } else {
            cp_wait<0>();
        }
        __syncthreads();                 // stage data visible to all warps

        // ---- Build A = wr*rz + rc into registers from smem.
        // Warp w owns rows {w, w+16, w+32, w+48, w+64}. Lane holds cols
        // lane, lane+32, and (lane<16) lane+64. LDS conflict-free.
        const float* __restrict__ wr_s = sbuf + stage * STAGE_FLOATS;
        const float* __restrict__ rz_s = wr_s + ARR_FLOATS;
        const float* __restrict__ rc_s = wr_s + 2 * ARR_FLOATS;
        float a0[5], a1[5], a2[5];
        #pragma unroll
        for (int r = 0; r < 5; ++r) {
            const int row = warp + (r << 4);
            const int o0 = row * NN + lane;
            const int o1 = o0 + 32;
            a0[r] = fmaf(wr_s[o0], rz_s[o0], rc_s[o0]);
            a1[r] = fmaf(wr_s[o1], rz_s[o1], rc_s[o1]);
            a2[r] = 0.0f;
            if (lane < 16) {
                const int o2 = o0 + 64;
                a2[r] = fmaf(wr_s[o2], rz_s[o2], rc_s[o2]);
            }
        }
        if (tid < NN) v[tid] = 0.11180339887498949f;   // 1/sqrt(80)
        __syncthreads();                 // build done (buffer now reusable)

        // Fused matvec + dots: wv = A v ; s_n2 = wv.wv ; s_ev = v.wv
        auto mv = [&]() {
            const float vr0 = v[lane];
            const float vr1 = v[lane + 32];
            const float vr2 = (lane < 16) ? v[lane + 64] : 0.0f;
            float ww = 0.0f, vwa = 0.0f;
            #pragma unroll
            for (int r = 0; r < 5; ++r) {
                const int row = warp + (r << 4);
                float s = a0[r] * vr0;
                s = fmaf(a1[r], vr1, s);
                s = fmaf(a2[r], vr2, s);
                #pragma unroll
                for (int off = 16; off; off >>= 1)
                    s += __shfl_xor_sync(0xFFFFFFFFu, s, off);
                if (lane == 0) {
                    wv[row] = s;
                    ww  = fmaf(s, s, ww);
                    vwa = fmaf(v[row], s, vwa);
                }
            }
            if (lane == 0) { red_ww[warp] = ww; red_vw[warp] = vwa; }
            __syncthreads();
            if (tid == 0) {
                float sa = 0.0f, sb = 0.0f;
                #pragma unroll
                for (int k = 0; k < 16; ++k) { sa += red_ww[k]; sb += red_vw[k]; }
                s_n2 = sa; s_ev = sb;
            }
            __syncthreads();
        };

        // ---- ev0 = v0 . (A v0)
        mv();
        float ev = s_ev;

        // ---- scan body x60 with convergence break (v updated on converging step)
        for (int it = 0; it < MAX_ITERS; ++it) {
            const float inv = 1.0f / sqrtf(s_n2);
            if (tid < NN) v[tid] = wv[tid] * inv;      // v_new = Av/||Av||
            __syncthreads();
            mv();
            const float ev_new = s_ev;
            if (fabsf(ev - ev_new) < TOL) break;       // uniform branch
            ev = ev_new;
        }

        // ---- out[i] += v[i] * (T[p]/v[src]),  src = p / n
        if (tid < NN) {
            const float tval = weights_t[p] * t_paths[p];
            const float coef = tval / v[p / NN];
            atomicAdd(&out[tid], v[tid] * coef);
        }
        __syncthreads();                 // protect v before next pair's reinit
        stage ^= 1;
    }
}

extern "C" void kernel_launch(void* const* d_in, const int* in_sizes, int n_in,
                              void* d_out, int out_size) {
    // metadata order: 0:x (unused), 1:r_zeros, 2:r_const, 3:t_paths,
    //                 4:weights_t, 5:weights_r
    const float* r_zeros   = (const float*)d_in[1];
    const float* r_const   = (const float*)d_in[2];
    const float* t_paths   = (const float*)d_in[3];
    const float* weights_t = (const float*)d_in[4];
    const float* weights_r = (const float*)d_in[5];
    float* out = (float*)d_out;

    int dev = 0, sm = 0;
    cudaGetDevice(&dev);
    cudaDeviceGetAttribute(&sm, cudaDevAttrMultiProcessorCount, dev);
    if (sm <= 0) sm = 148;
    if (sm > PAIRS) sm = PAIRS;

    static bool attr_set = false;
    // (idempotent; safe to call every time — NOT a guard on work)
    cudaFuncSetAttribute(power_pipe, cudaFuncAttributeMaxDynamicSharedMemorySize,
                         2 * STAGE_BYTES);
    (void)attr_set;

    zero_out<<<1, NN>>>(out);
    power_pipe<<<sm, TPB, 2 * STAGE_BYTES>>>(r_zeros, r_const, t_paths,
                                             weights_t, weights_r, out, sm);
}

// round 5
// speedup vs baseline: 1.2028x; 1.2028x over previous
#include <cuda_runtime.h>
#include <math.h>

#define NN 80
#define PAIRS (NN * NN)          // 6400
#define MAX_ITERS 60
#define TOL 1e-3f
#define TPB 256

__global__ void zero_out(float* __restrict__ out) {
    out[threadIdx.x] = 0.0f;     // d_out is poisoned; we accumulate atomically
}

__global__ __launch_bounds__(TPB, 4)
void power_iter_kernel(const float* __restrict__ r_zeros,
                       const float* __restrict__ r_const,
                       const float* __restrict__ t_paths,
                       const float* __restrict__ weights_t,
                       const float* __restrict__ weights_r,
                       float* __restrict__ out) {
    __shared__ float v[NN];        // current eigenvector estimate
    __shared__ float wv[NN];       // w = A v
    __shared__ float red_ww[8];    // per-warp partials of w.w
    __shared__ float red_vw[8];    // per-warp partials of v.w

    const int p    = blockIdx.x;
    const int tid  = threadIdx.x;
    const int warp = tid >> 5;
    const int lane = tid & 31;

    // ---- Build A = weights_r * r_zeros + r_const DIRECTLY INTO REGISTERS.
    // Warp w owns rows {w, w+8, ..., w+72}. Lane holds cols lane, lane+32,
    // lane+64 (lane<16 only). All loads coalesced; streaming hint (read-once).
    const size_t base = (size_t)p * (NN * NN);
    const float* __restrict__ rz = r_zeros   + base;
    const float* __restrict__ rc = r_const   + base;
    const float* __restrict__ wr = weights_r + base;

    float a0[10], a1[10], a2[10];
    #pragma unroll
    for (int r = 0; r < 10; ++r) {
        const int row = warp + (r << 3);
        const int o0  = row * NN + lane;
        const int o1  = o0 + 32;
        a0[r] = fmaf(__ldcs(wr + o0), __ldcs(rz + o0), __ldcs(rc + o0));
        a1[r] = fmaf(__ldcs(wr + o1), __ldcs(rz + o1), __ldcs(rc + o1));
        a2[r] = 0.0f;
        if (lane < 16) {
            const int o2 = o0 + 64;
            a2[r] = fmaf(__ldcs(wr + o2), __ldcs(rz + o2), __ldcs(rc + o2));
        }
    }

    if (tid < NN) v[tid] = 0.11180339887498949f;  // 1/sqrt(80)
    __syncthreads();

    float n2, evd;  // per-thread copies of ||Av||^2 and v.(Av) (identical everywhere)

    // Fused matvec + dots. ONE barrier: after lane0s publish wv + per-warp
    // partials, every thread reduces the 8 partials locally (LDS broadcasts).
    auto mv = [&]() {
        const float vr0 = v[lane];
        const float vr1 = v[lane + 32];
        const float vr2 = (lane < 16) ? v[lane + 64] : 0.0f;
        float ww = 0.0f, vwa = 0.0f;
        #pragma unroll
        for (int r = 0; r < 10; ++r) {
            const int row = warp + (r << 3);
            float s = a0[r] * vr0;
            s = fmaf(a1[r], vr1, s);
            s = fmaf(a2[r], vr2, s);
            #pragma unroll
            for (int off = 16; off; off >>= 1)
                s += __shfl_xor_sync(0xFFFFFFFFu, s, off);
            if (lane == 0) {
                wv[row] = s;
                ww  = fmaf(s, s, ww);
                vwa = fmaf(v[row], s, vwa);
            }
        }
        if (lane == 0) { red_ww[warp] = ww; red_vw[warp] = vwa; }
        __syncthreads();
        float sa = 0.0f, sb = 0.0f;
        #pragma unroll
        for (int k = 0; k < 8; ++k) { sa += red_ww[k]; sb += red_vw[k]; }
        n2 = sa; evd = sb;   // bitwise identical in every thread
    };

    // ---- ev0 = v0 . (A v0)
    mv();
    float ev = evd;

    // ---- scan body x60 with convergence break (v updated on converging step)
    for (int it = 0; it < MAX_ITERS; ++it) {
        const float inv = 1.0f / sqrtf(n2);       // computed per-thread, identical
        if (tid < NN) v[tid] = wv[tid] * inv;     // v_new = Av / ||Av||
        __syncthreads();                           // v visible before mv reads
        mv();                                      // wv = A v_new ; evd = v_new.wv
        if (fabsf(ev - evd) < TOL) break;          // uniform branch
        ev = evd;
    }

    // ---- out[i] += v[i] * (T[p] / v[src]),  src = p / n  (atomic accumulate)
    if (tid < NN) {
        const float tval = weights_t[p] * t_paths[p];
        const float coef = tval / v[p / NN];
        atomicAdd(&out[tid], v[tid] * coef);
    }
}

extern "C" void kernel_launch(void* const* d_in, const int* in_sizes, int n_in,
                              void* d_out, int out_size) {
    // metadata order: 0:x (unused), 1:r_zeros, 2:r_const, 3:t_paths,
    //                 4:weights_t, 5:weights_r
    const float* r_zeros   = (const float*)d_in[1];
    const float* r_const   = (const float*)d_in[2];
    const float* t_paths   = (const float*)d_in[3];
    const float* weights_t = (const float*)d_in[4];
    const float* weights_r = (const float*)d_in[5];
    float* out = (float*)d_out;

    zero_out<<<1, NN>>>(out);
    power_iter_kernel<<<PAIRS, TPB>>>(r_zeros, r_const, t_paths, weights_t,
                                      weights_r, out);
}

// round 6
// speedup vs baseline: 1.7880x; 1.4865x over previous
#include <cuda_runtime.h>
#include <math.h>

#define NN 80
#define PAIRS (NN * NN)          // 6400
#define MAX_ITERS 60
#define TOL 1e-3f
#define TPB 256

__global__ void zero_out(float* __restrict__ out) {
    out[threadIdx.x] = 0.0f;     // d_out is poisoned; we accumulate atomically
}

// Block-wide dot helper state lives in shared; R2-proven structure.
__global__ __launch_bounds__(TPB, 4)
void power_iter_kernel(const float* __restrict__ r_zeros,
                       const float* __restrict__ r_const,
                       const float* __restrict__ t_paths,
                       const float* __restrict__ weights_t,
                       const float* __restrict__ weights_r,
                       float* __restrict__ out) {
    __shared__ float v[NN];        // current eigenvector estimate
    __shared__ float wv[NN];       // w = A v
    __shared__ float red_ww[8];    // per-warp partials of w.w
    __shared__ float red_vw[8];    // per-warp partials of v.w
    __shared__ float s_n2;         // broadcast: ||w||^2
    __shared__ float s_ev;         // broadcast: v . (A v)

    const int p    = blockIdx.x;
    const int tid  = threadIdx.x;
    const int warp = tid >> 5;
    const int lane = tid & 31;

    // ---- Build A = weights_r * r_zeros + r_const DIRECTLY INTO REGISTERS.
    // Warp w owns rows {w, w+8, ..., w+72}. Lane holds cols lane, lane+32,
    // lane+64 (lane<16 only). All loads coalesced; streaming hint (read-once).
    const size_t base = (size_t)p * (NN * NN);
    const float* __restrict__ rz = r_zeros   + base;
    const float* __restrict__ rc = r_const   + base;
    const float* __restrict__ wr = weights_r + base;

    float a0[10], a1[10], a2[10];
    #pragma unroll
    for (int r = 0; r < 10; ++r) {
        const int row = warp + (r << 3);
        const int o0  = row * NN + lane;
        const int o1  = o0 + 32;
        a0[r] = fmaf(__ldcs(wr + o0), __ldcs(rz + o0), __ldcs(rc + o0));
        a1[r] = fmaf(__ldcs(wr + o1), __ldcs(rz + o1), __ldcs(rc + o1));
        a2[r] = 0.0f;
        if (lane < 16) {
            const int o2 = o0 + 64;
            a2[r] = fmaf(__ldcs(wr + o2), __ldcs(rz + o2), __ldcs(rc + o2));
        }
    }

    if (tid < NN) v[tid] = 0.11180339887498949f;  // 1/sqrt(80)
    __syncthreads();

    // Fused matvec + dots: wv = A v ; s_n2 = wv.wv ; s_ev = v.wv
    // (R2-proven: lane0 publishes, tid0 serial-reduces, shared broadcast.)
    auto mv = [&]() {
        const float vr0 = v[lane];
        const float vr1 = v[lane + 32];
        const float vr2 = (lane < 16) ? v[lane + 64] : 0.0f;
        float ww = 0.0f, vwacc = 0.0f;
        #pragma unroll
        for (int r = 0; r < 10; ++r) {
            const int row = warp + (r << 3);
            float s = a0[r] * vr0;
            s = fmaf(a1[r], vr1, s);
            s = fmaf(a2[r], vr2, s);
            #pragma unroll
            for (int off = 16; off; off >>= 1)
                s += __shfl_xor_sync(0xFFFFFFFFu, s, off);
            if (lane == 0) {
                wv[row] = s;
                ww    = fmaf(s, s, ww);
                vwacc = fmaf(v[row], s, vwacc);
            }
        }
        if (lane == 0) { red_ww[warp] = ww; red_vw[warp] = vwacc; }
        __syncthreads();
        if (tid == 0) {
            float A = 0.0f, B = 0.0f;
            #pragma unroll
            for (int k = 0; k < 8; ++k) { A += red_ww[k]; B += red_vw[k]; }
            s_n2 = A; s_ev = B;
        }
        __syncthreads();
    };

    // ---- ev0 = v0 . (A v0)
    mv();
    float ev = s_ev;

    // ---- scan body x60 with convergence break (v updated on converging step)
    for (int it = 0; it < MAX_ITERS; ++it) {
        const float inv = 1.0f / sqrtf(s_n2);
        if (tid < NN) v[tid] = wv[tid] * inv;    // v_new = Av / ||Av||
        __syncthreads();
        mv();                                     // wv = A v_new ; s_ev = v_new.wv
        const float ev_new = s_ev;
        if (fabsf(ev - ev_new) < TOL) break;      // uniform (shared broadcast)
        ev = ev_new;
    }

    // ---- out[i] += v[i] * (T[p] / v[src]),  src = p / n  (atomic accumulate)
    if (tid < NN) {
        const float tval = weights_t[p] * t_paths[p];
        const float coef = tval / v[p / NN];
        atomicAdd(&out[tid], v[tid] * coef);
    }
}

extern "C" void kernel_launch(void* const* d_in, const int* in_sizes, int n_in,
                              void* d_out, int out_size) {
    // metadata order: 0:x (unused), 1:r_zeros, 2:r_const, 3:t_paths,
    //                 4:weights_t, 5:weights_r
    const float* r_zeros   = (const float*)d_in[1];
    const float* r_const   = (const float*)d_in[2];
    const float* t_paths   = (const float*)d_in[3];
    const float* weights_t = (const float*)d_in[4];
    const float* weights_r = (const float*)d_in[5];
    float* out = (float*)d_out;

    zero_out<<<1, NN>>>(out);
    power_iter_kernel<<<PAIRS, TPB>>>(r_zeros, r_const, t_paths, weights_t,
                                      weights_r, out);
}